// round 3
// baseline (speedup 1.0000x reference)
#include <cuda_runtime.h>

// Problem constants (fixed by the reference).
#define NB 8192   // batch
#define NH 1024   // hidden
#define NO 256    // out features
#define NE 16     // experts

// GEMM tiling
#define BM 128
#define BN 128
#define BK 16
#define NIT (NH / BK)     // 64 mainloop iterations
#define THREADS 256
#define LDA 20            // smem row stride (uint): 16B-aligned, conflict-free frag loads

// --- scratch (no allocs allowed) ---
__device__ int g_bin[NE][NB];   // fixed-capacity per-expert bins of sample ids
__device__ int g_counts[NE];

// ---------------- pass 1: zero counters ----------------
__global__ void zero_kernel() {
    if (threadIdx.x < NE) g_counts[threadIdx.x] = 0;
}

// ---------------- pass 2: classify + scatter in one pass ----------------
// NOTE: JAX default x64-disabled -> num/c are int32 on device.
__global__ void bin_kernel(const int* __restrict__ num,
                           const int* __restrict__ c, int cmap_n) {
    int i = blockIdx.x * blockDim.x + threadIdx.x;
    if (i < NB) {
        int idx = num[i];
        idx = min(max(idx, 0), cmap_n - 1);
        int e = c[idx] & (NE - 1);
        int pos = atomicAdd(&g_counts[e], 1);
        g_bin[e][pos] = i;
    }
}

// ---------------- TF32 helpers ----------------
__device__ __forceinline__ unsigned f2tf(float f) {
    unsigned u;
    asm("cvt.rna.tf32.f32 %0, %1;" : "=r"(u) : "f"(f));
    return u;
}

__device__ __forceinline__ void mma_tf32(float c[4],
                                         unsigned a0, unsigned a1, unsigned a2, unsigned a3,
                                         unsigned b0, unsigned b1) {
    asm volatile(
        "mma.sync.aligned.m16n8k8.row.col.f32.tf32.tf32.f32 "
        "{%0,%1,%2,%3}, {%4,%5,%6,%7}, {%8,%9}, {%0,%1,%2,%3};"
        : "+f"(c[0]), "+f"(c[1]), "+f"(c[2]), "+f"(c[3])
        : "r"(a0), "r"(a1), "r"(a2), "r"(a3), "r"(b0), "r"(b1));
}

// ---------------- pass 3: per-expert TF32 tensor-core GEMM + bias + sigmoid ----------------
// grid = (NO/BN=2, ceil(NB/BM)=64, NE=16); blocks past an expert's row count exit.
__global__ __launch_bounds__(THREADS, 3)
void gemm_kernel(const float* __restrict__ x,
                 const float* __restrict__ W,
                 const float* __restrict__ bias,
                 float* __restrict__ out) {
    const int e = blockIdx.z;
    const int rows = g_counts[e];
    const int m_start = blockIdx.y * BM;
    if (m_start >= rows) return;
    const int n_start = blockIdx.x * BN;
    const int* __restrict__ perm = g_bin[e];

    __shared__ unsigned As[2][BM][LDA];   // As[buf][m][k]  (tf32 bits)
    __shared__ unsigned Bs[2][BN][LDA];   // Bs[buf][n][k]
    __shared__ float bsm[BN];
    __shared__ int   prm[BM];

    const int t    = threadIdx.x;
    const int lane = t & 31;
    const int wid  = t >> 5;
    const int g    = lane >> 2;   // groupID
    const int tig  = lane & 3;    // threadID_in_group
    const int warp_m = (wid & 1) * 64;    // 2 warps along M (64 rows each)
    const int warp_n = (wid >> 1) * 32;   // 4 warps along N (32 cols each)

    // staging coords: thread t loads 8 k-contiguous floats of row lm
    const int lm   = t >> 1;          // 0..127
    const int koff = (t & 1) * 8;     // 0 or 8

    if (t < BN) bsm[t] = bias[e * NO + n_start + t];
    if (t < BM) {
        int m = m_start + t;
        prm[t] = (m < rows) ? perm[m] : perm[m_start];  // clamp to a valid row
    }
    __syncthreads();

    const float* xrowp = x + (size_t)prm[lm] * NH + koff;
    const float* wrowp = W + ((size_t)e * NO + n_start + lm) * NH + koff;

    float acc[4][4][4];
    #pragma unroll
    for (int i = 0; i < 4; i++)
        #pragma unroll
        for (int j = 0; j < 4; j++)
            #pragma unroll
            for (int q = 0; q < 4; q++) acc[i][j][q] = 0.f;

    float4 pa0, pa1, pb0, pb1;
    // prologue: load k-slab 0
    pa0 = *(const float4*)(xrowp);
    pa1 = *(const float4*)(xrowp + 4);
    pb0 = *(const float4*)(wrowp);
    pb1 = *(const float4*)(wrowp + 4);
    *(uint4*)&As[0][lm][koff]     = make_uint4(f2tf(pa0.x), f2tf(pa0.y), f2tf(pa0.z), f2tf(pa0.w));
    *(uint4*)&As[0][lm][koff + 4] = make_uint4(f2tf(pa1.x), f2tf(pa1.y), f2tf(pa1.z), f2tf(pa1.w));
    *(uint4*)&Bs[0][lm][koff]     = make_uint4(f2tf(pb0.x), f2tf(pb0.y), f2tf(pb0.z), f2tf(pb0.w));
    *(uint4*)&Bs[0][lm][koff + 4] = make_uint4(f2tf(pb1.x), f2tf(pb1.y), f2tf(pb1.z), f2tf(pb1.w));
    __syncthreads();

    int buf = 0;
    for (int it = 0; it < NIT; ++it) {
        // prefetch next k-slab from GMEM
        if (it + 1 < NIT) {
            const float* xp = xrowp + (it + 1) * BK;
            const float* wp = wrowp + (it + 1) * BK;
            pa0 = *(const float4*)(xp);
            pa1 = *(const float4*)(xp + 4);
            pb0 = *(const float4*)(wp);
            pb1 = *(const float4*)(wp + 4);
        }

        // compute on current buffer: 2 k-steps of m16n8k8
        #pragma unroll
        for (int kk = 0; kk < 2; kk++) {
            const int kb = kk * 8;
            unsigned a[4][4], b[4][2];
            #pragma unroll
            for (int mf = 0; mf < 4; mf++) {
                const int r = warp_m + mf * 16 + g;
                a[mf][0] = As[buf][r][kb + tig];
                a[mf][1] = As[buf][r + 8][kb + tig];
                a[mf][2] = As[buf][r][kb + tig + 4];
                a[mf][3] = As[buf][r + 8][kb + tig + 4];
            }
            #pragma unroll
            for (int nf = 0; nf < 4; nf++) {
                const int n = warp_n + nf * 8 + g;
                b[nf][0] = Bs[buf][n][kb + tig];
                b[nf][1] = Bs[buf][n][kb + tig + 4];
            }
            #pragma unroll
            for (int mf = 0; mf < 4; mf++)
                #pragma unroll
                for (int nf = 0; nf < 4; nf++)
                    mma_tf32(acc[mf][nf], a[mf][0], a[mf][1], a[mf][2], a[mf][3],
                             b[nf][0], b[nf][1]);
        }

        // stage prefetched slab into the other buffer
        if (it + 1 < NIT) {
            const int nb = buf ^ 1;
            *(uint4*)&As[nb][lm][koff]     = make_uint4(f2tf(pa0.x), f2tf(pa0.y), f2tf(pa0.z), f2tf(pa0.w));
            *(uint4*)&As[nb][lm][koff + 4] = make_uint4(f2tf(pa1.x), f2tf(pa1.y), f2tf(pa1.z), f2tf(pa1.w));
            *(uint4*)&Bs[nb][lm][koff]     = make_uint4(f2tf(pb0.x), f2tf(pb0.y), f2tf(pb0.z), f2tf(pb0.w));
            *(uint4*)&Bs[nb][lm][koff + 4] = make_uint4(f2tf(pb1.x), f2tf(pb1.y), f2tf(pb1.z), f2tf(pb1.w));
        }
        __syncthreads();
        buf ^= 1;
    }

    // epilogue: bias + sigmoid, scatter rows through the bin
    #pragma unroll
    for (int mf = 0; mf < 4; mf++) {
        #pragma unroll
        for (int h = 0; h < 2; h++) {
            const int rl = warp_m + mf * 16 + g + h * 8;   // local row
            if (m_start + rl < rows) {
                const int row = prm[rl];
                #pragma unroll
                for (int nf = 0; nf < 4; nf++) {
                    const int col = warp_n + nf * 8 + 2 * tig;
                    float v0 = acc[mf][nf][h * 2 + 0] + bsm[col];
                    float v1 = acc[mf][nf][h * 2 + 1] + bsm[col + 1];
                    float2 o;
                    o.x = 1.f / (1.f + __expf(-v0));
                    o.y = 1.f / (1.f + __expf(-v1));
                    *(float2*)&out[(size_t)row * NO + n_start + col] = o;
                }
            }
        }
    }
}

extern "C" void kernel_launch(void* const* d_in, const int* in_sizes, int n_in,
                              void* d_out, int out_size) {
    const float* x    = (const float*)d_in[0];   // [B, H]
    const float* W    = (const float*)d_in[1];   // [E, O, H]
    const float* bias = (const float*)d_in[2];   // [E, O]
    const int*   num  = (const int*)d_in[3];     // [B]    int32
    const int*   c    = (const int*)d_in[4];     // [CMAP] int32
    float* out = (float*)d_out;                  // [B, O]

    const int cmap_n = in_sizes[4];

    zero_kernel<<<1, 32>>>();
    bin_kernel<<<NB / 256, 256>>>(num, c, cmap_n);

    dim3 grid(NO / BN, NB / BM, NE);   // (2, 64, 16); dead tiles exit immediately
    gemm_kernel<<<grid, THREADS>>>(x, W, bias, out);
}

// round 4
// speedup vs baseline: 2.9294x; 2.9294x over previous
#include <cuda_runtime.h>

// Problem constants (fixed by the reference).
#define NB 8192   // batch
#define NH 1024   // hidden
#define NO 256    // out features
#define NE 16     // experts

// GEMM tiling
#define BM 128
#define BN 128
#define BK 16
#define NIT (NH / BK)     // 64 mainloop iterations
#define THREADS 256
#define LDA 20            // smem row stride (uint): 16B-aligned, conflict-free frag loads

// --- scratch (no allocs allowed) ---
__device__ int g_bin[NE][NB];   // fixed-capacity per-expert bins of sample ids
__device__ int g_counts[NE];

// ---------------- pass 1: zero counters ----------------
__global__ void zero_kernel() {
    if (threadIdx.x < NE) g_counts[threadIdx.x] = 0;
}

// ---------------- pass 2: classify + scatter in one pass ----------------
// NOTE: JAX default x64-disabled -> num/c are int32 on device.
__global__ void bin_kernel(const int* __restrict__ num,
                           const int* __restrict__ c, int cmap_n) {
    int i = blockIdx.x * blockDim.x + threadIdx.x;
    if (i < NB) {
        int idx = num[i];
        idx = min(max(idx, 0), cmap_n - 1);
        int e = c[idx] & (NE - 1);
        int pos = atomicAdd(&g_counts[e], 1);
        g_bin[e][pos] = i;
    }
}

// ---------------- TF32 helpers ----------------
__device__ __forceinline__ unsigned f2tf(float f) {
    unsigned u;
    asm("cvt.rna.tf32.f32 %0, %1;" : "=r"(u) : "f"(f));
    return u;
}

__device__ __forceinline__ void mma_tf32(float c[4],
                                         unsigned a0, unsigned a1, unsigned a2, unsigned a3,
                                         unsigned b0, unsigned b1) {
    asm volatile(
        "mma.sync.aligned.m16n8k8.row.col.f32.tf32.tf32.f32 "
        "{%0,%1,%2,%3}, {%4,%5,%6,%7}, {%8,%9}, {%0,%1,%2,%3};"
        : "+f"(c[0]), "+f"(c[1]), "+f"(c[2]), "+f"(c[3])
        : "r"(a0), "r"(a1), "r"(a2), "r"(a3), "r"(b0), "r"(b1));
}

// ---------------- pass 3: per-expert TF32 tensor-core GEMM + bias + sigmoid ----------------
// grid = (NO/BN=2, ceil(NB/BM)=64, NE=16); blocks past an expert's row count exit.
// IMPORTANT: no min-blocks bound — ~150 live CTAs over 148 SMs run at occupancy 1;
// capping regs at 84 (256,3) caused massive spilling in R3.
__global__ __launch_bounds__(THREADS)
void gemm_kernel(const float* __restrict__ x,
                 const float* __restrict__ W,
                 const float* __restrict__ bias,
                 float* __restrict__ out) {
    const int e = blockIdx.z;
    const int rows = g_counts[e];
    const int m_start = blockIdx.y * BM;
    if (m_start >= rows) return;
    const int n_start = blockIdx.x * BN;
    const int* __restrict__ perm = g_bin[e];

    __shared__ unsigned As[2][BM][LDA];   // As[buf][m][k]  (tf32 bits)
    __shared__ unsigned Bs[2][BN][LDA];   // Bs[buf][n][k]
    __shared__ float bsm[BN];
    __shared__ int   prm[BM];

    const int t    = threadIdx.x;
    const int lane = t & 31;
    const int wid  = t >> 5;
    const int g    = lane >> 2;   // groupID
    const int tig  = lane & 3;    // threadID_in_group
    const int warp_m = (wid & 1) * 64;    // 2 warps along M (64 rows each)
    const int warp_n = (wid >> 1) * 32;   // 4 warps along N (32 cols each)

    // staging coords: thread t loads 8 k-contiguous floats of row lm
    const int lm   = t >> 1;          // 0..127
    const int koff = (t & 1) * 8;     // 0 or 8

    if (t < BN) bsm[t] = bias[e * NO + n_start + t];
    if (t < BM) {
        int m = m_start + t;
        prm[t] = (m < rows) ? perm[m] : perm[m_start];  // clamp to a valid row
    }
    __syncthreads();

    const float* xrowp = x + (size_t)prm[lm] * NH + koff;
    const float* wrowp = W + ((size_t)e * NO + n_start + lm) * NH + koff;

    float acc[4][4][4];
    #pragma unroll
    for (int i = 0; i < 4; i++)
        #pragma unroll
        for (int j = 0; j < 4; j++)
            #pragma unroll
            for (int q = 0; q < 4; q++) acc[i][j][q] = 0.f;

    float4 pa0, pa1, pb0, pb1;
    // prologue: load k-slab 0
    pa0 = *(const float4*)(xrowp);
    pa1 = *(const float4*)(xrowp + 4);
    pb0 = *(const float4*)(wrowp);
    pb1 = *(const float4*)(wrowp + 4);
    *(uint4*)&As[0][lm][koff]     = make_uint4(f2tf(pa0.x), f2tf(pa0.y), f2tf(pa0.z), f2tf(pa0.w));
    *(uint4*)&As[0][lm][koff + 4] = make_uint4(f2tf(pa1.x), f2tf(pa1.y), f2tf(pa1.z), f2tf(pa1.w));
    *(uint4*)&Bs[0][lm][koff]     = make_uint4(f2tf(pb0.x), f2tf(pb0.y), f2tf(pb0.z), f2tf(pb0.w));
    *(uint4*)&Bs[0][lm][koff + 4] = make_uint4(f2tf(pb1.x), f2tf(pb1.y), f2tf(pb1.z), f2tf(pb1.w));
    __syncthreads();

    int buf = 0;
    #pragma unroll 2
    for (int it = 0; it < NIT; ++it) {
        // prefetch next k-slab from GMEM
        if (it + 1 < NIT) {
            const float* xp = xrowp + (it + 1) * BK;
            const float* wp = wrowp + (it + 1) * BK;
            pa0 = *(const float4*)(xp);
            pa1 = *(const float4*)(xp + 4);
            pb0 = *(const float4*)(wp);
            pb1 = *(const float4*)(wp + 4);
        }

        // compute on current buffer: 2 k-steps of m16n8k8
        #pragma unroll
        for (int kk = 0; kk < 2; kk++) {
            const int kb = kk * 8;
            unsigned a[4][4], b[4][2];
            #pragma unroll
            for (int mf = 0; mf < 4; mf++) {
                const int r = warp_m + mf * 16 + g;
                a[mf][0] = As[buf][r][kb + tig];
                a[mf][1] = As[buf][r + 8][kb + tig];
                a[mf][2] = As[buf][r][kb + tig + 4];
                a[mf][3] = As[buf][r + 8][kb + tig + 4];
            }
            #pragma unroll
            for (int nf = 0; nf < 4; nf++) {
                const int n = warp_n + nf * 8 + g;
                b[nf][0] = Bs[buf][n][kb + tig];
                b[nf][1] = Bs[buf][n][kb + tig + 4];
            }
            #pragma unroll
            for (int mf = 0; mf < 4; mf++)
                #pragma unroll
                for (int nf = 0; nf < 4; nf++)
                    mma_tf32(acc[mf][nf], a[mf][0], a[mf][1], a[mf][2], a[mf][3],
                             b[nf][0], b[nf][1]);
        }

        // stage prefetched slab into the other buffer
        if (it + 1 < NIT) {
            const int nb = buf ^ 1;
            *(uint4*)&As[nb][lm][koff]     = make_uint4(f2tf(pa0.x), f2tf(pa0.y), f2tf(pa0.z), f2tf(pa0.w));
            *(uint4*)&As[nb][lm][koff + 4] = make_uint4(f2tf(pa1.x), f2tf(pa1.y), f2tf(pa1.z), f2tf(pa1.w));
            *(uint4*)&Bs[nb][lm][koff]     = make_uint4(f2tf(pb0.x), f2tf(pb0.y), f2tf(pb0.z), f2tf(pb0.w));
            *(uint4*)&Bs[nb][lm][koff + 4] = make_uint4(f2tf(pb1.x), f2tf(pb1.y), f2tf(pb1.z), f2tf(pb1.w));
        }
        __syncthreads();
        buf ^= 1;
    }

    // epilogue: bias + sigmoid, scatter rows through the bin
    #pragma unroll
    for (int mf = 0; mf < 4; mf++) {
        #pragma unroll
        for (int h = 0; h < 2; h++) {
            const int rl = warp_m + mf * 16 + g + h * 8;   // local row
            if (m_start + rl < rows) {
                const int row = prm[rl];
                #pragma unroll
                for (int nf = 0; nf < 4; nf++) {
                    const int col = warp_n + nf * 8 + 2 * tig;
                    float v0 = acc[mf][nf][h * 2 + 0] + bsm[col];
                    float v1 = acc[mf][nf][h * 2 + 1] + bsm[col + 1];
                    float2 o;
                    o.x = 1.f / (1.f + __expf(-v0));
                    o.y = 1.f / (1.f + __expf(-v1));
                    *(float2*)&out[(size_t)row * NO + n_start + col] = o;
                }
            }
        }
    }
}

extern "C" void kernel_launch(void* const* d_in, const int* in_sizes, int n_in,
                              void* d_out, int out_size) {
    const float* x    = (const float*)d_in[0];   // [B, H]
    const float* W    = (const float*)d_in[1];   // [E, O, H]
    const float* bias = (const float*)d_in[2];   // [E, O]
    const int*   num  = (const int*)d_in[3];     // [B]    int32
    const int*   c    = (const int*)d_in[4];     // [CMAP] int32
    float* out = (float*)d_out;                  // [B, O]

    const int cmap_n = in_sizes[4];

    zero_kernel<<<1, 32>>>();
    bin_kernel<<<NB / 256, 256>>>(num, c, cmap_n);

    dim3 grid(NO / BN, NB / BM, NE);   // (2, 64, 16); dead tiles exit immediately
    gemm_kernel<<<grid, THREADS>>>(x, W, bias, out);
}

// round 7
// speedup vs baseline: 5.8571x; 1.9994x over previous
#include <cuda_runtime.h>
#include <cuda_fp16.h>
#include <cstdint>

// Problem constants.
#define NB 8192
#define NH 1024
#define NO 256
#define NE 16

// GEMM tiling: CTA = 128x128, K slabs of 32.
#define BM 128
#define BN 128
#define BKS 32
#define NSLAB (NH / BKS)   // 32
#define THREADS 256
#define LDH 40             // halfs per smem row (80 B): conflict-free ldmatrix phases

// --- scratch (no allocs allowed) ---
__device__ int g_bin[NE][NB];
__device__ int g_counts[NE];

__global__ void zero_kernel() {
    if (threadIdx.x < NE) g_counts[threadIdx.x] = 0;
}

__global__ void bin_kernel(const int* __restrict__ num,
                           const int* __restrict__ c, int cmap_n) {
    int i = blockIdx.x * blockDim.x + threadIdx.x;
    if (i < NB) {
        int idx = num[i];
        idx = min(max(idx, 0), cmap_n - 1);
        int e = c[idx] & (NE - 1);
        int pos = atomicAdd(&g_counts[e], 1);
        g_bin[e][pos] = i;
    }
}

// ---------------- helpers ----------------
__device__ __forceinline__ uint32_t smem_u32(const void* p) {
    uint32_t a;
    asm("{ .reg .u64 t; cvta.to.shared.u64 t, %1; cvt.u32.u64 %0, t; }" : "=r"(a) : "l"(p));
    return a;
}

__device__ __forceinline__ void ldsm_x4(uint32_t r[4], uint32_t addr) {
    asm volatile("ldmatrix.sync.aligned.m8n8.x4.shared.b16 {%0,%1,%2,%3}, [%4];"
                 : "=r"(r[0]), "=r"(r[1]), "=r"(r[2]), "=r"(r[3]) : "r"(addr));
}

__device__ __forceinline__ void mma_f16(float c[4], const uint32_t a[4],
                                        uint32_t b0, uint32_t b1) {
    asm volatile(
        "mma.sync.aligned.m16n8k16.row.col.f32.f16.f16.f32 "
        "{%0,%1,%2,%3}, {%4,%5,%6,%7}, {%8,%9}, {%0,%1,%2,%3};"
        : "+f"(c[0]), "+f"(c[1]), "+f"(c[2]), "+f"(c[3])
        : "r"(a[0]), "r"(a[1]), "r"(a[2]), "r"(a[3]), "r"(b0), "r"(b1));
}

__device__ __forceinline__ float sigf(float v) { return 1.f / (1.f + __expf(-v)); }

__device__ __forceinline__ void stage16(__half* dst, const float4 v[4]) {
    __half2 h[8];
    h[0] = __floats2half2_rn(v[0].x, v[0].y);
    h[1] = __floats2half2_rn(v[0].z, v[0].w);
    h[2] = __floats2half2_rn(v[1].x, v[1].y);
    h[3] = __floats2half2_rn(v[1].z, v[1].w);
    h[4] = __floats2half2_rn(v[2].x, v[2].y);
    h[5] = __floats2half2_rn(v[2].z, v[2].w);
    h[6] = __floats2half2_rn(v[3].x, v[3].y);
    h[7] = __floats2half2_rn(v[3].z, v[3].w);
    *(uint4*)(dst)     = *(uint4*)&h[0];
    *(uint4*)(dst + 8) = *(uint4*)&h[4];
}

// ---------------- fp16 tensor-core GEMM + bias + sigmoid ----------------
// grid = (NO/BN=2, NB/BM=64, NE=16); dead tiles exit immediately.
__global__ __launch_bounds__(THREADS)
void gemm_kernel(const float* __restrict__ x,
                 const float* __restrict__ W,
                 const float* __restrict__ bias,
                 float* __restrict__ out) {
    const int e = blockIdx.z;
    const int rows = g_counts[e];
    const int m_start = blockIdx.y * BM;
    if (m_start >= rows) return;
    const int n_start = blockIdx.x * BN;

    __shared__ __half As[2][BM][LDH];   // A[m][k]  fp16
    __shared__ __half Bs[2][BN][LDH];   // B[n][k]  fp16 (k contiguous = col-major for mma)
    __shared__ float  bsm[BN];
    __shared__ int    prm[BM];

    const int t    = threadIdx.x;
    const int lane = t & 31;
    const int wid  = t >> 5;
    const int g    = lane >> 2;   // mma C-fragment group
    const int tig  = lane & 3;
    const int g2   = lane >> 3;   // ldmatrix lane group (0..3)
    const int lr   = lane & 7;
    const int warp_m = (wid & 1) * 64;
    const int warp_n = (wid >> 1) * 32;

    // staging coords: thread t covers 16 k-floats of row (t>>1), half (t&1)
    const int row  = t >> 1;
    const int half = t & 1;

    if (t < BN) bsm[t] = bias[e * NO + n_start + t];
    if (t < BM) {
        int m = m_start + t;
        prm[t] = (m < rows) ? g_bin[e][m] : g_bin[e][m_start];
    }
    __syncthreads();

    const int prow = prm[row];
    const float* xs = x + (size_t)prow * NH + half * 16;
    const float* ws = W + ((size_t)e * NO + n_start + row) * NH + half * 16;

    // ldmatrix byte offsets (both operands NON-trans: k is contiguous in smem).
    // A matrices 0..3 = rows m+{0,8} x k+{0,8} -> a0..a3
    uint32_t aoff[4], boff[2];
    #pragma unroll
    for (int mf = 0; mf < 4; mf++)
        aoff[mf] = (uint32_t)((warp_m + mf * 16 + (g2 & 1) * 8 + lr) * (LDH * 2) + (g2 >> 1) * 16);
    // B matrices 0..3 = n+{0,0,8,8} x k+{0,8,0,8} -> b[p][0..3]
    #pragma unroll
    for (int p = 0; p < 2; p++)
        boff[p] = (uint32_t)((warp_n + p * 16 + (g2 >> 1) * 8 + lr) * (LDH * 2) + (g2 & 1) * 16);

    const uint32_t As_b = smem_u32(As);
    const uint32_t Bs_b = smem_u32(Bs);
    const uint32_t BUFA = BM * LDH * 2;   // bytes per A buffer
    const uint32_t BUFB = BN * LDH * 2;

    float acc[4][4][4];
    #pragma unroll
    for (int i = 0; i < 4; i++)
        #pragma unroll
        for (int j = 0; j < 4; j++)
            #pragma unroll
            for (int q = 0; q < 4; q++) acc[i][j][q] = 0.f;

    float4 xa[4], wb[4];
    // prologue: slab 0
    #pragma unroll
    for (int i = 0; i < 4; i++) xa[i] = ((const float4*)xs)[i];
    #pragma unroll
    for (int i = 0; i < 4; i++) wb[i] = ((const float4*)ws)[i];
    stage16(&As[0][row][half * 16], xa);
    stage16(&Bs[0][row][half * 16], wb);
    __syncthreads();

    #pragma unroll 2
    for (int ks = 0; ks < NSLAB; ks++) {
        const int buf = ks & 1;

        if (ks + 1 < NSLAB) {
            const float* xp = xs + (ks + 1) * BKS;
            const float* wp = ws + (ks + 1) * BKS;
            #pragma unroll
            for (int i = 0; i < 4; i++) xa[i] = ((const float4*)xp)[i];
            #pragma unroll
            for (int i = 0; i < 4; i++) wb[i] = ((const float4*)wp)[i];
        }

        const uint32_t ab = As_b + buf * BUFA;
        const uint32_t bb = Bs_b + buf * BUFB;
        #pragma unroll
        for (int kk = 0; kk < 2; kk++) {
            uint32_t a[4][4], b[2][4];
            #pragma unroll
            for (int mf = 0; mf < 4; mf++) ldsm_x4(a[mf], ab + aoff[mf] + kk * 32);
            #pragma unroll
            for (int p = 0; p < 2; p++)   ldsm_x4(b[p], bb + boff[p] + kk * 32);
            #pragma unroll
            for (int mf = 0; mf < 4; mf++)
                #pragma unroll
                for (int nf = 0; nf < 4; nf++)
                    mma_f16(acc[mf][nf], a[mf], b[nf >> 1][(nf & 1) * 2],
                            b[nf >> 1][(nf & 1) * 2 + 1]);
        }

        if (ks + 1 < NSLAB) {
            stage16(&As[buf ^ 1][row][half * 16], xa);
            stage16(&Bs[buf ^ 1][row][half * 16], wb);
        }
        __syncthreads();
    }

    // epilogue: bias + sigmoid, scatter rows through the bin
    #pragma unroll
    for (int mf = 0; mf < 4; mf++) {
        #pragma unroll
        for (int h = 0; h < 2; h++) {
            const int rl = warp_m + mf * 16 + g + h * 8;
            if (m_start + rl < rows) {
                const int orow = prm[rl];
                #pragma unroll
                for (int nf = 0; nf < 4; nf++) {
                    const int col = warp_n + nf * 8 + 2 * tig;
                    float v0 = acc[mf][nf][h * 2 + 0] + bsm[col];
                    float v1 = acc[mf][nf][h * 2 + 1] + bsm[col + 1];
                    float2 o;
                    o.x = sigf(v0);
                    o.y = sigf(v1);
                    *(float2*)&out[(size_t)orow * NO + n_start + col] = o;
                }
            }
        }
    }
}

extern "C" void kernel_launch(void* const* d_in, const int* in_sizes, int n_in,
                              void* d_out, int out_size) {
    const float* x    = (const float*)d_in[0];   // [B, H]
    const float* W    = (const float*)d_in[1];   // [E, O, H]
    const float* bias = (const float*)d_in[2];   // [E, O]
    const int*   num  = (const int*)d_in[3];     // [B]    int32
    const int*   c    = (const int*)d_in[4];     // [CMAP] int32
    float* out = (float*)d_out;                  // [B, O]

    const int cmap_n = in_sizes[4];

    zero_kernel<<<1, 32>>>();
    bin_kernel<<<NB / 256, 256>>>(num, c, cmap_n);

    dim3 grid(NO / BN, NB / BM, NE);   // (2, 64, 16)
    gemm_kernel<<<grid, THREADS>>>(x, W, bias, out);
}